// round 15
// baseline (speedup 1.0000x reference)
#include <cuda_runtime.h>

typedef unsigned long long ULL;
typedef unsigned int U32;

// ---------------- device scratch (no allocations allowed) ----------------
__device__ float g_UV[8 * 64 * 64 * 9 * 2];      // (u,v) per (b,h,w,n)
__device__ float g_Wt[1152 * 128];               // Wt[k][cout]
__device__ float g_xT[8 * 4096 * 128];           // NHWC transpose of x (16.8 MB)

// ---------------- packed f32x2 helpers ----------------
__device__ __forceinline__ ULL pack2(float lo, float hi) {
    ULL r; asm("mov.b64 %0, {%1,%2};" : "=l"(r) : "f"(lo), "f"(hi)); return r;
}
__device__ __forceinline__ void unpack2(ULL v, float& lo, float& hi) {
    asm("mov.b64 {%0,%1}, %2;" : "=f"(lo), "=f"(hi) : "l"(v));
}
__device__ __forceinline__ void fma2(ULL& d, ULL a, ULL b) {
    asm("fma.rn.f32x2 %0, %1, %2, %0;" : "+l"(d) : "l"(a), "l"(b));
}
__device__ __forceinline__ void cp_async16(U32 saddr, const void* gptr) {
    asm volatile("cp.async.ca.shared.global [%0], [%1], 16;\n"
                 :: "r"(saddr), "l"(gptr) : "memory");
}

// ============================================================================
// Fused prologue, 512 threads, LONG blocks FIRST:
//   [0, 128):      offset conv (two 64-ch halves) + sampling-coord epilogue
//   [128, 2176):   NCHW -> NHWC transpose (2 tiles per block)
//   [2176, 2464):  weight transpose Wt[k][cout] = w_ker[cout][c][tap]
// ============================================================================
__global__ void __launch_bounds__(512) k_prep(const float* __restrict__ x,
                                              const float* __restrict__ w_off,
                                              const float* __restrict__ b_off,
                                              const float* __restrict__ w_ker) {
    __shared__ __align__(16) float sbuf[8064];

    const int tid = threadIdx.x;
    const int bid = blockIdx.x;

    if (bid < 128) {
        // ---- offset conv, 16x16 tile, 512 threads: halves reduce 64 ch each
        float* sxA = sbuf;            // [2][2592]
        float* swA = sbuf + 5184;     // [2][1440]
        const int half = tid >> 8;
        const int p    = tid & 255;
        const int b  = bid >> 4;
        const int h0 = ((bid >> 2) & 3) * 16, w0 = (bid & 3) * 16;
        const int px = p & 15, py = p >> 4;

        ULL acc[10];
        if (half == 0) {
#pragma unroll
            for (int i = 0; i < 9; ++i) acc[i] = pack2(b_off[2 * i], b_off[2 * i + 1]);
            acc[9] = pack2(0.f, 0.f);
        } else {
#pragma unroll
            for (int i = 0; i < 10; ++i) acc[i] = pack2(0.f, 0.f);
        }

        float* msx = sxA + half * 2592;
        float* msw = swA + half * 1440;

        for (int i = 0; i < 8; ++i) {
            const int cc = (i << 1) | half;
            for (int e = p; e < 2592; e += 256) {
                int c = e / 324; int rem = e - c * 324;
                int r = rem / 18, col = rem - r * 18;
                int gh = h0 + r - 1, gw = w0 + col - 1;
                float v = 0.f;
                if (gh >= 0 && gh < 64 && gw >= 0 && gw < 64)
                    v = x[((b * 128 + cc * 8 + c) << 12) + (gh << 6) + gw];
                msx[e] = v;
            }
            for (int e = p; e < 1440; e += 256) {
                int c = e / 180; int rem = e - c * 180;
                int tap = rem / 20, o = rem - tap * 20;
                msw[(c * 9 + tap) * 20 + o] =
                    (o < 18) ? w_off[(o * 128 + cc * 8 + c) * 9 + tap] : 0.f;
            }
            __syncthreads();

#pragma unroll
            for (int c = 0; c < 8; ++c) {
#pragma unroll
                for (int ii = 0; ii < 3; ++ii) {
#pragma unroll
                    for (int j = 0; j < 3; ++j) {
                        float xv = msx[c * 324 + (py + ii) * 18 + (px + j)];
                        ULL xp = pack2(xv, xv);
                        const ulonglong2* wp =
                            (const ulonglong2*)&msw[(c * 9 + ii * 3 + j) * 20];
                        ulonglong2 wA = wp[0], wB = wp[1], wC = wp[2], wD = wp[3], wE = wp[4];
                        fma2(acc[0], xp, wA.x); fma2(acc[1], xp, wA.y);
                        fma2(acc[2], xp, wB.x); fma2(acc[3], xp, wB.y);
                        fma2(acc[4], xp, wC.x); fma2(acc[5], xp, wC.y);
                        fma2(acc[6], xp, wD.x); fma2(acc[7], xp, wD.y);
                        fma2(acc[8], xp, wE.x); fma2(acc[9], xp, wE.y);
                    }
                }
            }
            __syncthreads();
        }

        float offs[18];
#pragma unroll
        for (int i = 0; i < 9; ++i) unpack2(acc[i], offs[2 * i], offs[2 * i + 1]);

        if (half == 1) {
#pragma unroll
            for (int j = 0; j < 18; ++j) sbuf[p * 20 + j] = offs[j];
        }
        __syncthreads();
        if (half == 0) {
#pragma unroll
            for (int j = 0; j < 18; ++j) offs[j] += sbuf[p * 20 + j];

            const int h = h0 + py, w = w0 + px;
            float2* uvp = (float2*)g_UV;
            const int basei = (b * 4096 + h * 64 + w) * 9;
#pragma unroll
            for (int n = 0; n < 9; ++n) {
                float u = (float)(h + n / 3 - 1) + offs[n];
                float v = (float)(w + n % 3 - 1) + offs[9 + n];
                u = fminf(fmaxf(u, 0.f), 63.f);
                v = fminf(fmaxf(v, 0.f), 63.f);
                uvp[basei + n] = make_float2(u, v);
            }
        }
        return;
    }

    if (bid < 2176) {
        // ---- NCHW -> NHWC transpose, 2 tiles per 512-thread block
        int t = ((bid - 128) << 1) | (tid >> 8);
        int p = tid & 255;
        float* tr = sbuf + (tid >> 8) * 1056;   // 32*33 per tile
        int s0 = (t & 127) << 5;
        int c0 = ((t >> 7) & 3) << 5;
        int b  = t >> 9;
        int tx = p & 31, ty = p >> 5;           // (32, 8)
#pragma unroll
        for (int i = 0; i < 4; ++i) {
            int c = c0 + ty + i * 8;
            tr[(ty + i * 8) * 33 + tx] = x[((b * 128 + c) << 12) + s0 + tx];
        }
        __syncthreads();
#pragma unroll
        for (int i = 0; i < 4; ++i) {
            int s = s0 + ty + i * 8;
            g_xT[(((b << 12) + s) << 7) + c0 + tx] = tr[tx * 33 + ty + i * 8];
        }
        return;
    }

    // ---- weight transpose (288 blocks x 512 = 147456 = 1152*128)
    {
        int i = (bid - 2176) * 512 + tid;
        int o = i / 1152, k = i - o * 1152;
        g_Wt[k * 128 + o] = w_ker[i];
    }
}

// ============================================================================
// Kernel: halo-smem bilinear gather + GEMM with intra-chunk pipelining.
//   Block: M=128 pixels (16h x 8w) x N=128 cout.  K=1152 in 16 chunks of 72.
//   sA k-rows reordered rnew = n*8 + c  ->  taps 0..2 = rows 0..23.
//   Per chunk: expose gather(n<3); gather(n>=3) overlaps GEMM(rows 0..23);
//   then GEMM(rows 24..71).  100.9 KB smem -> 2 blocks/SM, 256 blocks, 1 wave.
// ============================================================================
#define SA_GP    580
#define HPITCH   17
#define SMEM_SB   0                                  // 72*128*4   = 36864
#define SMEM_SA   36864                              // 16*580*4   = 37120
#define SMEM_H    73984                              // 24*17*8*4  = 13056
#define SMEM_CODE 87040                              // 1152*4
#define SMEM_FX   91648                              // 1152*4
#define SMEM_FY   96256                              // 1152*4
#define SMEM_TOT  100864

#define GSTEP(rn, ro) do {                                                    \
    float4 aL = *(const float4*)(aRow + ((rn) << 3));                         \
    float4 aH = *(const float4*)(aRow + ((rn) << 3) + 4);                     \
    ulonglong2 bl0 = *(const ulonglong2*)&sB[(ro) * 128 + (tx << 3)];         \
    ulonglong2 bl1 = *(const ulonglong2*)&sB[(ro) * 128 + (tx << 3) + 4];     \
    ULL a0 = pack2(aL.x, aL.x), a1 = pack2(aL.y, aL.y);                       \
    ULL a2 = pack2(aL.z, aL.z), a3 = pack2(aL.w, aL.w);                       \
    ULL a4 = pack2(aH.x, aH.x), a5 = pack2(aH.y, aH.y);                       \
    ULL a6 = pack2(aH.z, aH.z), a7 = pack2(aH.w, aH.w);                       \
    fma2(acc[0][0], a0, bl0.x); fma2(acc[0][1], a0, bl0.y);                   \
    fma2(acc[0][2], a0, bl1.x); fma2(acc[0][3], a0, bl1.y);                   \
    fma2(acc[1][0], a1, bl0.x); fma2(acc[1][1], a1, bl0.y);                   \
    fma2(acc[1][2], a1, bl1.x); fma2(acc[1][3], a1, bl1.y);                   \
    fma2(acc[2][0], a2, bl0.x); fma2(acc[2][1], a2, bl0.y);                   \
    fma2(acc[2][2], a2, bl1.x); fma2(acc[2][3], a2, bl1.y);                   \
    fma2(acc[3][0], a3, bl0.x); fma2(acc[3][1], a3, bl0.y);                   \
    fma2(acc[3][2], a3, bl1.x); fma2(acc[3][3], a3, bl1.y);                   \
    fma2(acc[4][0], a4, bl0.x); fma2(acc[4][1], a4, bl0.y);                   \
    fma2(acc[4][2], a4, bl1.x); fma2(acc[4][3], a4, bl1.y);                   \
    fma2(acc[5][0], a5, bl0.x); fma2(acc[5][1], a5, bl0.y);                   \
    fma2(acc[5][2], a5, bl1.x); fma2(acc[5][3], a5, bl1.y);                   \
    fma2(acc[6][0], a6, bl0.x); fma2(acc[6][1], a6, bl0.y);                   \
    fma2(acc[6][2], a6, bl1.x); fma2(acc[6][3], a6, bl1.y);                   \
    fma2(acc[7][0], a7, bl0.x); fma2(acc[7][1], a7, bl0.y);                   \
    fma2(acc[7][2], a7, bl1.x); fma2(acc[7][3], a7, bl1.y);                   \
} while (0)

__global__ void __launch_bounds__(256, 2) k_gemm(const float* __restrict__ b_ker,
                                                 float* __restrict__ out) {
    extern __shared__ char smem[];
    float* sB    = (float*)(smem + SMEM_SB);
    float* sA    = (float*)(smem + SMEM_SA);
    float* sH    = (float*)(smem + SMEM_H);
    int*   sCode = (int*)  (smem + SMEM_CODE);
    float* sFx   = (float*)(smem + SMEM_FX);
    float* sFy   = (float*)(smem + SMEM_FY);
    const U32 sB_u32 = (U32)__cvta_generic_to_shared(sB);

    const int tid = threadIdx.x;
    const int b  = blockIdx.z;
    const int h0 = blockIdx.y * 16, w0 = blockIdx.x * 8;
    const int warp = tid >> 5, lane = tid & 31;
    const int ty = ((warp & 1) << 3) | (lane >> 2);   // 0..15 pixel-group
    const int tx = ((warp >> 1) << 2) | (lane & 3);   // 0..15 cout-group
    const int pm  = tid & 127;                        // gather pixel
    const int chg = tid >> 7;                         // gather channel half

    const float* xTb = g_xT + ((long)b << 19);

    // halo-fill constants (3 float4 units per thread)
    int hsrc[3], hdst[3];
#pragma unroll
    for (int it = 0; it < 3; ++it) {
        int e = tid + (it << 8);
        int pos = e >> 1, g = e & 1;
        int hr = pos >> 4, wr = pos & 15;
        int gh = min(max(h0 - 4 + hr, 0), 63);
        int gw = min(max(w0 - 4 + wr, 0), 63);
        hsrc[it] = (((gh << 6) + gw) << 7) + (g << 2);
        hdst[it] = (hr * HPITCH + wr) * 8 + (g << 2);
    }

    // ---- stage sampling meta once per block, keyed [n][pm]
    const float2* uvp = (const float2*)g_UV;
    for (int e = tid; e < 1152; e += 256) {
        int n = e >> 7, pp = e & 127;
        int h = h0 + (pp >> 3), w = w0 + (pp & 7);
        float2 uv = uvp[(b * 4096 + h * 64 + w) * 9 + n];
        float xf = floorf(uv.x), yf = floorf(uv.y);
        int ix = (int)xf, iy = (int)yf;
        int gcode = ix * 64 + iy;
        if (ix < 63) gcode |= (1 << 12);
        if (iy < 63) gcode |= (1 << 13);
        int hr = ix - (h0 - 4), wr = iy - (w0 - 4);
        int hcode = (hr * HPITCH + wr) & 4095;
        if (ix < 63) hcode |= (1 << 12);
        if (iy < 63) hcode |= (1 << 13);
        if (hr >= 0 && hr < 23 && wr >= 0 && wr < 15) hcode |= (1 << 14);
        sCode[e] = hcode | (gcode << 16);
        sFx[e] = uv.x - xf;
        sFy[e] = uv.y - yf;
    }

    ULL acc[8][4];
#pragma unroll
    for (int m = 0; m < 8; ++m)
#pragma unroll
        for (int j = 0; j < 4; ++j) acc[m][j] = pack2(0.f, 0.f);

    const int sa_base = (pm >> 3) * SA_GP + (pm & 7);
    const float* aRow = sA + ty * SA_GP;
    __syncthreads();

    for (int cc = 0; cc < 16; ++cc) {
        const int chbase = cc * 8;

        // ---- B tile cp.async (sB free: previous GEMM done at loop-end sync)
        {
            const float* wsrc = g_Wt + cc * 72 * 128;
#pragma unroll
            for (int it = 0; it < 9; ++it) {
                int e = tid + (it << 8);
                cp_async16(sB_u32 + e * 16, wsrc + e * 4);
            }
            asm volatile("cp.async.commit_group;\n" ::: "memory");
        }

        // ---- halo fill, direct (coalesced 64B rows from NHWC)
#pragma unroll
        for (int it = 0; it < 3; ++it)
            *(float4*)&sH[hdst[it]] = *(const float4*)(xTb + hsrc[it] + chbase);
        __syncthreads();                      // (a) halo visible

        // ---- gather helper (bilinear from halo, global fallback)
#define GATHER(n) do {                                                        \
        int p = ((n) << 7) + pm;                                              \
        float fx = sFx[p], fy = sFy[p];                                       \
        int code = sCode[p];                                                  \
        float4 v00, v01, v10, v11;                                            \
        if (code & (1 << 14)) {                                               \
            const float* cb = sH + ((code & 4095) << 3) + (chg << 2);         \
            int dxs = (code & (1 << 12)) ? (HPITCH * 8) : 0;                  \
            int dys = (code & (1 << 13)) ? 8 : 0;                             \
            v00 = *(const float4*)(cb);                                       \
            v01 = *(const float4*)(cb + dys);                                 \
            v10 = *(const float4*)(cb + dxs);                                 \
            v11 = *(const float4*)(cb + dxs + dys);                           \
        } else {                                                              \
            int gc = code >> 16;                                              \
            const float* pb = xTb + ((long)(gc & 4095) << 7) + chbase + (chg << 2); \
            int dxs = (gc & (1 << 12)) ? 8192 : 0;                            \
            int dys = (gc & (1 << 13)) ? 128  : 0;                            \
            v00 = *(const float4*)(pb);                                       \
            v01 = *(const float4*)(pb + dys);                                 \
            v10 = *(const float4*)(pb + dxs);                                 \
            v11 = *(const float4*)(pb + dxs + dys);                           \
        }                                                                     \
        int ab = sa_base + ((((n) << 3) + (chg << 2)) << 3);                  \
        float r0, r1;                                                         \
        r0 = v00.x + fy * (v01.x - v00.x);                                    \
        r1 = v10.x + fy * (v11.x - v10.x);                                    \
        sA[ab     ] = r0 + fx * (r1 - r0);                                    \
        r0 = v00.y + fy * (v01.y - v00.y);                                    \
        r1 = v10.y + fy * (v11.y - v10.y);                                    \
        sA[ab + 8 ] = r0 + fx * (r1 - r0);                                    \
        r0 = v00.z + fy * (v01.z - v00.z);                                    \
        r1 = v10.z + fy * (v11.z - v10.z);                                    \
        sA[ab + 16] = r0 + fx * (r1 - r0);                                    \
        r0 = v00.w + fy * (v01.w - v00.w);                                    \
        r1 = v10.w + fy * (v11.w - v10.w);                                    \
        sA[ab + 24] = r0 + fx * (r1 - r0);                                    \
    } while (0)

        // ---- exposed gather: taps 0..2 (sA rows 0..23)
        GATHER(0); GATHER(1); GATHER(2);
        asm volatile("cp.async.wait_group 0;\n" ::: "memory");
        __syncthreads();                      // (b) rows 0..23 + sB visible

        // ---- overlapped: gather taps 3..8 (rows 24..71) + GEMM rows 0..23
        GATHER(3); GATHER(4); GATHER(5);
        GATHER(6); GATHER(7); GATHER(8);
#pragma unroll
        for (int n = 0; n < 3; ++n)
#pragma unroll
            for (int ci = 0; ci < 8; ++ci)
                GSTEP(n * 8 + ci, ci * 9 + n);
        __syncthreads();                      // (c) rows 24..71 visible

        // ---- GEMM rows 24..71
#pragma unroll
        for (int n = 3; n < 9; ++n)
#pragma unroll
            for (int ci = 0; ci < 8; ++ci)
                GSTEP(n * 8 + ci, ci * 9 + n);
        __syncthreads();                      // (d) before next B/halo overwrite
    }

    // ---- epilogue: + bias.  Thread owns row h0+ty, w0..w0+7, couts tx*8+0..7.
    const int co0 = tx << 3;
    const int h = h0 + ty;
    float* op = out + (((long)(b * 128 + co0)) << 12) + (h << 6) + w0;
#pragma unroll
    for (int j = 0; j < 4; ++j) {
        float lo[8], hi[8];
#pragma unroll
        for (int m = 0; m < 8; ++m) unpack2(acc[m][j], lo[m], hi[m]);
        float bkl = b_ker[co0 + 2 * j];
        float bkh = b_ker[co0 + 2 * j + 1];
        float* o0 = op + ((long)(2 * j) << 12);
        float* o1 = op + ((long)(2 * j + 1) << 12);
        *(float4*)(o0)     = make_float4(lo[0] + bkl, lo[1] + bkl, lo[2] + bkl, lo[3] + bkl);
        *(float4*)(o0 + 4) = make_float4(lo[4] + bkl, lo[5] + bkl, lo[6] + bkl, lo[7] + bkl);
        *(float4*)(o1)     = make_float4(hi[0] + bkh, hi[1] + bkh, hi[2] + bkh, hi[3] + bkh);
        *(float4*)(o1 + 4) = make_float4(hi[4] + bkh, hi[5] + bkh, hi[6] + bkh, hi[7] + bkh);
    }
}

// ============================================================================
// launch
// ============================================================================
extern "C" void kernel_launch(void* const* d_in, const int* in_sizes, int n_in,
                              void* d_out, int out_size) {
    const float* x     = (const float*)d_in[0];
    const float* w_off = (const float*)d_in[1];
    const float* b_off = (const float*)d_in[2];
    const float* w_ker = (const float*)d_in[3];
    const float* b_ker = (const float*)d_in[4];
    float* out = (float*)d_out;

    cudaFuncSetAttribute(k_gemm, cudaFuncAttributeMaxDynamicSharedMemorySize,
                         SMEM_TOT);

    k_prep<<<2464, 512, 0, 0>>>(x, w_off, b_off, w_ker);
    k_gemm<<<dim3(8, 4, 8), 256, SMEM_TOT, 0>>>(b_ker, out);
}

// round 16
// speedup vs baseline: 1.1464x; 1.1464x over previous
#include <cuda_runtime.h>

typedef unsigned long long ULL;
typedef unsigned int U32;

// ---------------- device scratch (no allocations allowed) ----------------
__device__ float g_UV[8 * 64 * 64 * 9 * 2];      // (u,v) per (b,h,w,n)
__device__ float g_Wt[1152 * 128];               // Wt[k][cout]
__device__ float g_xT[8 * 4096 * 128];           // NHWC transpose of x (16.8 MB)

// ---------------- packed f32x2 helpers ----------------
__device__ __forceinline__ ULL pack2(float lo, float hi) {
    ULL r; asm("mov.b64 %0, {%1,%2};" : "=l"(r) : "f"(lo), "f"(hi)); return r;
}
__device__ __forceinline__ void unpack2(ULL v, float& lo, float& hi) {
    asm("mov.b64 {%0,%1}, %2;" : "=f"(lo), "=f"(hi) : "l"(v));
}
__device__ __forceinline__ void fma2(ULL& d, ULL a, ULL b) {
    asm("fma.rn.f32x2 %0, %1, %2, %0;" : "+l"(d) : "l"(a), "l"(b));
}
__device__ __forceinline__ void cp_async16(U32 saddr, const void* gptr) {
    asm volatile("cp.async.ca.shared.global [%0], [%1], 16;\n"
                 :: "r"(saddr), "l"(gptr) : "memory");
}

// ============================================================================
// Kernel 0: NCHW -> NHWC transpose.  x (8,128,4096) -> g_xT (8,4096,128)
// ============================================================================
__global__ void __launch_bounds__(256) k_tr(const float* __restrict__ x) {
    __shared__ float t[32][33];
    const int b  = blockIdx.z;
    const int s0 = blockIdx.x * 32;
    const int c0 = blockIdx.y * 32;
    const int tx = threadIdx.x, ty = threadIdx.y;   // (32, 8)
#pragma unroll
    for (int i = 0; i < 4; ++i) {
        int c = c0 + ty + i * 8;
        t[ty + i * 8][tx] = x[((b * 128 + c) << 12) + s0 + tx];
    }
    __syncthreads();
#pragma unroll
    for (int i = 0; i < 4; ++i) {
        int s = s0 + ty + i * 8;
        g_xT[(((b << 12) + s) << 7) + c0 + tx] = t[tx][ty + i * 8];
    }
}

// ============================================================================
// Kernel 1: offset conv (128->18, 3x3, pad 1), 512 threads: two halves each
// reduce 64 channels (even/odd 8-ch chunks), combined via smem at the end.
// ============================================================================
__global__ void __launch_bounds__(512) k_offset(const float* __restrict__ x,
                                                const float* __restrict__ w_off,
                                                const float* __restrict__ b_off) {
    __shared__ __align__(16) float sbuf[8064];
    float* sxA = sbuf;            // [2][2592]
    float* swA = sbuf + 5184;     // [2][1440]

    const int tid  = threadIdx.x;
    const int half = tid >> 8;
    const int p    = tid & 255;
    const int b  = blockIdx.z;
    const int h0 = blockIdx.y * 16, w0 = blockIdx.x * 16;
    const int px = p & 15, py = p >> 4;

    ULL acc[10];
    if (half == 0) {
#pragma unroll
        for (int i = 0; i < 9; ++i) acc[i] = pack2(b_off[2 * i], b_off[2 * i + 1]);
        acc[9] = pack2(0.f, 0.f);
    } else {
#pragma unroll
        for (int i = 0; i < 10; ++i) acc[i] = pack2(0.f, 0.f);
    }

    float* msx = sxA + half * 2592;
    float* msw = swA + half * 1440;

    for (int i = 0; i < 8; ++i) {
        const int cc = (i << 1) | half;
        for (int e = p; e < 2592; e += 256) {
            int c = e / 324; int rem = e - c * 324;
            int r = rem / 18, col = rem - r * 18;
            int gh = h0 + r - 1, gw = w0 + col - 1;
            float v = 0.f;
            if (gh >= 0 && gh < 64 && gw >= 0 && gw < 64)
                v = x[((b * 128 + cc * 8 + c) << 12) + (gh << 6) + gw];
            msx[e] = v;
        }
        for (int e = p; e < 1440; e += 256) {
            int c = e / 180; int rem = e - c * 180;
            int tap = rem / 20, o = rem - tap * 20;
            msw[(c * 9 + tap) * 20 + o] =
                (o < 18) ? w_off[(o * 128 + cc * 8 + c) * 9 + tap] : 0.f;
        }
        __syncthreads();

#pragma unroll
        for (int c = 0; c < 8; ++c) {
#pragma unroll
            for (int ii = 0; ii < 3; ++ii) {
#pragma unroll
                for (int j = 0; j < 3; ++j) {
                    float xv = msx[c * 324 + (py + ii) * 18 + (px + j)];
                    ULL xp = pack2(xv, xv);
                    const ulonglong2* wp =
                        (const ulonglong2*)&msw[(c * 9 + ii * 3 + j) * 20];
                    ulonglong2 wA = wp[0], wB = wp[1], wC = wp[2], wD = wp[3], wE = wp[4];
                    fma2(acc[0], xp, wA.x); fma2(acc[1], xp, wA.y);
                    fma2(acc[2], xp, wB.x); fma2(acc[3], xp, wB.y);
                    fma2(acc[4], xp, wC.x); fma2(acc[5], xp, wC.y);
                    fma2(acc[6], xp, wD.x); fma2(acc[7], xp, wD.y);
                    fma2(acc[8], xp, wE.x); fma2(acc[9], xp, wE.y);
                }
            }
        }
        __syncthreads();
    }

    float offs[18];
#pragma unroll
    for (int i = 0; i < 9; ++i) unpack2(acc[i], offs[2 * i], offs[2 * i + 1]);

    if (half == 1) {
#pragma unroll
        for (int j = 0; j < 18; ++j) sbuf[p * 20 + j] = offs[j];
    }
    __syncthreads();
    if (half == 0) {
#pragma unroll
        for (int j = 0; j < 18; ++j) offs[j] += sbuf[p * 20 + j];

        const int h = h0 + py, w = w0 + px;
        float2* uvp = (float2*)g_UV;
        const int basei = (b * 4096 + h * 64 + w) * 9;
#pragma unroll
        for (int n = 0; n < 9; ++n) {
            float u = (float)(h + n / 3 - 1) + offs[n];
            float v = (float)(w + n % 3 - 1) + offs[9 + n];
            u = fminf(fmaxf(u, 0.f), 63.f);
            v = fminf(fmaxf(v, 0.f), 63.f);
            uvp[basei + n] = make_float2(u, v);
        }
    }
}

// ============================================================================
// Kernel 2: weight transpose  Wt[k = c*9+tap][cout] = w_ker[cout][c][tap]
// ============================================================================
__global__ void k_wt(const float* __restrict__ w_ker) {
    int i = blockIdx.x * 256 + threadIdx.x;
    if (i < 1152 * 128) {
        int o = i / 1152, k = i - o * 1152;
        g_Wt[k * 128 + o] = w_ker[i];
    }
}

// ============================================================================
// Kernel 3: halo-smem bilinear gather + GEMM with intra-chunk pipelining.
//   (identical to R15's k_gemm — measured 269 us)
//   Block: M=128 pixels (16h x 8w) x N=128 cout.  K=1152 in 16 chunks of 72.
//   sA k-rows reordered rnew = n*8 + c  ->  taps 0..2 = rows 0..23.
//   Per chunk: expose gather(n<3); gather(n>=3) overlaps GEMM(rows 0..23);
//   then GEMM(rows 24..71).  100.9 KB smem -> 2 blocks/SM, 256 blocks, 1 wave.
// ============================================================================
#define SA_GP    580
#define HPITCH   17
#define SMEM_SB   0                                  // 72*128*4   = 36864
#define SMEM_SA   36864                              // 16*580*4   = 37120
#define SMEM_H    73984                              // 24*17*8*4  = 13056
#define SMEM_CODE 87040                              // 1152*4
#define SMEM_FX   91648                              // 1152*4
#define SMEM_FY   96256                              // 1152*4
#define SMEM_TOT  100864

#define GSTEP(rn, ro) do {                                                    \
    float4 aL = *(const float4*)(aRow + ((rn) << 3));                         \
    float4 aH = *(const float4*)(aRow + ((rn) << 3) + 4);                     \
    ulonglong2 bl0 = *(const ulonglong2*)&sB[(ro) * 128 + (tx << 3)];         \
    ulonglong2 bl1 = *(const ulonglong2*)&sB[(ro) * 128 + (tx << 3) + 4];     \
    ULL a0 = pack2(aL.x, aL.x), a1 = pack2(aL.y, aL.y);                       \
    ULL a2 = pack2(aL.z, aL.z), a3 = pack2(aL.w, aL.w);                       \
    ULL a4 = pack2(aH.x, aH.x), a5 = pack2(aH.y, aH.y);                       \
    ULL a6 = pack2(aH.z, aH.z), a7 = pack2(aH.w, aH.w);                       \
    fma2(acc[0][0], a0, bl0.x); fma2(acc[0][1], a0, bl0.y);                   \
    fma2(acc[0][2], a0, bl1.x); fma2(acc[0][3], a0, bl1.y);                   \
    fma2(acc[1][0], a1, bl0.x); fma2(acc[1][1], a1, bl0.y);                   \
    fma2(acc[1][2], a1, bl1.x); fma2(acc[1][3], a1, bl1.y);                   \
    fma2(acc[2][0], a2, bl0.x); fma2(acc[2][1], a2, bl0.y);                   \
    fma2(acc[2][2], a2, bl1.x); fma2(acc[2][3], a2, bl1.y);                   \
    fma2(acc[3][0], a3, bl0.x); fma2(acc[3][1], a3, bl0.y);                   \
    fma2(acc[3][2], a3, bl1.x); fma2(acc[3][3], a3, bl1.y);                   \
    fma2(acc[4][0], a4, bl0.x); fma2(acc[4][1], a4, bl0.y);                   \
    fma2(acc[4][2], a4, bl1.x); fma2(acc[4][3], a4, bl1.y);                   \
    fma2(acc[5][0], a5, bl0.x); fma2(acc[5][1], a5, bl0.y);                   \
    fma2(acc[5][2], a5, bl1.x); fma2(acc[5][3], a5, bl1.y);                   \
    fma2(acc[6][0], a6, bl0.x); fma2(acc[6][1], a6, bl0.y);                   \
    fma2(acc[6][2], a6, bl1.x); fma2(acc[6][3], a6, bl1.y);                   \
    fma2(acc[7][0], a7, bl0.x); fma2(acc[7][1], a7, bl0.y);                   \
    fma2(acc[7][2], a7, bl1.x); fma2(acc[7][3], a7, bl1.y);                   \
} while (0)

__global__ void __launch_bounds__(256, 2) k_gemm(const float* __restrict__ b_ker,
                                                 float* __restrict__ out) {
    extern __shared__ char smem[];
    float* sB    = (float*)(smem + SMEM_SB);
    float* sA    = (float*)(smem + SMEM_SA);
    float* sH    = (float*)(smem + SMEM_H);
    int*   sCode = (int*)  (smem + SMEM_CODE);
    float* sFx   = (float*)(smem + SMEM_FX);
    float* sFy   = (float*)(smem + SMEM_FY);
    const U32 sB_u32 = (U32)__cvta_generic_to_shared(sB);

    const int tid = threadIdx.x;
    const int b  = blockIdx.z;
    const int h0 = blockIdx.y * 16, w0 = blockIdx.x * 8;
    const int warp = tid >> 5, lane = tid & 31;
    const int ty = ((warp & 1) << 3) | (lane >> 2);   // 0..15 pixel-group
    const int tx = ((warp >> 1) << 2) | (lane & 3);   // 0..15 cout-group
    const int pm  = tid & 127;                        // gather pixel
    const int chg = tid >> 7;                         // gather channel half

    const float* xTb = g_xT + ((long)b << 19);

    // halo-fill constants (3 float4 units per thread)
    int hsrc[3], hdst[3];
#pragma unroll
    for (int it = 0; it < 3; ++it) {
        int e = tid + (it << 8);
        int pos = e >> 1, g = e & 1;
        int hr = pos >> 4, wr = pos & 15;
        int gh = min(max(h0 - 4 + hr, 0), 63);
        int gw = min(max(w0 - 4 + wr, 0), 63);
        hsrc[it] = (((gh << 6) + gw) << 7) + (g << 2);
        hdst[it] = (hr * HPITCH + wr) * 8 + (g << 2);
    }

    // ---- stage sampling meta once per block, keyed [n][pm]
    const float2* uvp = (const float2*)g_UV;
    for (int e = tid; e < 1152; e += 256) {
        int n = e >> 7, pp = e & 127;
        int h = h0 + (pp >> 3), w = w0 + (pp & 7);
        float2 uv = uvp[(b * 4096 + h * 64 + w) * 9 + n];
        float xf = floorf(uv.x), yf = floorf(uv.y);
        int ix = (int)xf, iy = (int)yf;
        int gcode = ix * 64 + iy;
        if (ix < 63) gcode |= (1 << 12);
        if (iy < 63) gcode |= (1 << 13);
        int hr = ix - (h0 - 4), wr = iy - (w0 - 4);
        int hcode = (hr * HPITCH + wr) & 4095;
        if (ix < 63) hcode |= (1 << 12);
        if (iy < 63) hcode |= (1 << 13);
        if (hr >= 0 && hr < 23 && wr >= 0 && wr < 15) hcode |= (1 << 14);
        sCode[e] = hcode | (gcode << 16);
        sFx[e] = uv.x - xf;
        sFy[e] = uv.y - yf;
    }

    ULL acc[8][4];
#pragma unroll
    for (int m = 0; m < 8; ++m)
#pragma unroll
        for (int j = 0; j < 4; ++j) acc[m][j] = pack2(0.f, 0.f);

    const int sa_base = (pm >> 3) * SA_GP + (pm & 7);
    const float* aRow = sA + ty * SA_GP;
    __syncthreads();

    for (int cc = 0; cc < 16; ++cc) {
        const int chbase = cc * 8;

        // ---- B tile cp.async (sB free: previous GEMM done at loop-end sync)
        {
            const float* wsrc = g_Wt + cc * 72 * 128;
#pragma unroll
            for (int it = 0; it < 9; ++it) {
                int e = tid + (it << 8);
                cp_async16(sB_u32 + e * 16, wsrc + e * 4);
            }
            asm volatile("cp.async.commit_group;\n" ::: "memory");
        }

        // ---- halo fill, direct (coalesced 64B rows from NHWC)
#pragma unroll
        for (int it = 0; it < 3; ++it)
            *(float4*)&sH[hdst[it]] = *(const float4*)(xTb + hsrc[it] + chbase);
        __syncthreads();                      // (a) halo visible

#define GATHER(n) do {                                                        \
        int p = ((n) << 7) + pm;                                              \
        float fx = sFx[p], fy = sFy[p];                                       \
        int code = sCode[p];                                                  \
        float4 v00, v01, v10, v11;                                            \
        if (code & (1 << 14)) {                                               \
            const float* cb = sH + ((code & 4095) << 3) + (chg << 2);         \
            int dxs = (code & (1 << 12)) ? (HPITCH * 8) : 0;                  \
            int dys = (code & (1 << 13)) ? 8 : 0;                             \
            v00 = *(const float4*)(cb);                                       \
            v01 = *(const float4*)(cb + dys);                                 \
            v10 = *(const float4*)(cb + dxs);                                 \
            v11 = *(const float4*)(cb + dxs + dys);                           \
        } else {                                                              \
            int gc = code >> 16;                                              \
            const float* pb = xTb + ((long)(gc & 4095) << 7) + chbase + (chg << 2); \
            int dxs = (gc & (1 << 12)) ? 8192 : 0;                            \
            int dys = (gc & (1 << 13)) ? 128  : 0;                            \
            v00 = *(const float4*)(pb);                                       \
            v01 = *(const float4*)(pb + dys);                                 \
            v10 = *(const float4*)(pb + dxs);                                 \
            v11 = *(const float4*)(pb + dxs + dys);                           \
        }                                                                     \
        int ab = sa_base + ((((n) << 3) + (chg << 2)) << 3);                  \
        float r0, r1;                                                         \
        r0 = v00.x + fy * (v01.x - v00.x);                                    \
        r1 = v10.x + fy * (v11.x - v10.x);                                    \
        sA[ab     ] = r0 + fx * (r1 - r0);                                    \
        r0 = v00.y + fy * (v01.y - v00.y);                                    \
        r1 = v10.y + fy * (v11.y - v10.y);                                    \
        sA[ab + 8 ] = r0 + fx * (r1 - r0);                                    \
        r0 = v00.z + fy * (v01.z - v00.z);                                    \
        r1 = v10.z + fy * (v11.z - v10.z);                                    \
        sA[ab + 16] = r0 + fx * (r1 - r0);                                    \
        r0 = v00.w + fy * (v01.w - v00.w);                                    \
        r1 = v10.w + fy * (v11.w - v10.w);                                    \
        sA[ab + 24] = r0 + fx * (r1 - r0);                                    \
    } while (0)

        // ---- exposed gather: taps 0..2 (sA rows 0..23)
        GATHER(0); GATHER(1); GATHER(2);
        asm volatile("cp.async.wait_group 0;\n" ::: "memory");
        __syncthreads();                      // (b) rows 0..23 + sB visible

        // ---- overlapped: gather taps 3..8 (rows 24..71) + GEMM rows 0..23
        GATHER(3); GATHER(4); GATHER(5);
        GATHER(6); GATHER(7); GATHER(8);
#pragma unroll
        for (int n = 0; n < 3; ++n)
#pragma unroll
            for (int ci = 0; ci < 8; ++ci)
                GSTEP(n * 8 + ci, ci * 9 + n);
        __syncthreads();                      // (c) rows 24..71 visible

        // ---- GEMM rows 24..71
#pragma unroll
        for (int n = 3; n < 9; ++n)
#pragma unroll
            for (int ci = 0; ci < 8; ++ci)
                GSTEP(n * 8 + ci, ci * 9 + n);
        __syncthreads();                      // (d) before next B/halo overwrite
    }

    // ---- epilogue: + bias.  Thread owns row h0+ty, w0..w0+7, couts tx*8+0..7.
    const int co0 = tx << 3;
    const int h = h0 + ty;
    float* op = out + (((long)(b * 128 + co0)) << 12) + (h << 6) + w0;
#pragma unroll
    for (int j = 0; j < 4; ++j) {
        float lo[8], hi[8];
#pragma unroll
        for (int m = 0; m < 8; ++m) unpack2(acc[m][j], lo[m], hi[m]);
        float bkl = b_ker[co0 + 2 * j];
        float bkh = b_ker[co0 + 2 * j + 1];
        float* o0 = op + ((long)(2 * j) << 12);
        float* o1 = op + ((long)(2 * j + 1) << 12);
        *(float4*)(o0)     = make_float4(lo[0] + bkl, lo[1] + bkl, lo[2] + bkl, lo[3] + bkl);
        *(float4*)(o0 + 4) = make_float4(lo[4] + bkl, lo[5] + bkl, lo[6] + bkl, lo[7] + bkl);
        *(float4*)(o1)     = make_float4(hi[0] + bkh, hi[1] + bkh, hi[2] + bkh, hi[3] + bkh);
        *(float4*)(o1 + 4) = make_float4(hi[4] + bkh, hi[5] + bkh, hi[6] + bkh, hi[7] + bkh);
    }
}

// ============================================================================
// launch
// ============================================================================
extern "C" void kernel_launch(void* const* d_in, const int* in_sizes, int n_in,
                              void* d_out, int out_size) {
    const float* x     = (const float*)d_in[0];
    const float* w_off = (const float*)d_in[1];
    const float* b_off = (const float*)d_in[2];
    const float* w_ker = (const float*)d_in[3];
    const float* b_ker = (const float*)d_in[4];
    float* out = (float*)d_out;

    cudaFuncSetAttribute(k_gemm, cudaFuncAttributeMaxDynamicSharedMemorySize,
                         SMEM_TOT);

    k_wt<<<(1152 * 128 + 255) / 256, 256, 0, 0>>>(w_ker);
    k_tr<<<dim3(128, 4, 8), dim3(32, 8), 0, 0>>>(x);
    k_offset<<<dim3(4, 4, 8), 512, 0, 0>>>(x, w_off, b_off);
    k_gemm<<<dim3(8, 4, 8), 256, SMEM_TOT, 0>>>(b_ker, out);
}